// round 5
// baseline (speedup 1.0000x reference)
#include <cuda_runtime.h>
#include <math.h>

#define N_NODES 4096
#define NFEAT   128
#define NHID    128
#define NHEADS  4
#define NCLASS  32
#define KEDGE   32
#define ALPHA_LRELU 0.2f

// ---------------- scratch ----------------
__device__ float g_h  [N_NODES * NHEADS * NHID];   // [n][head*128+d]
__device__ float g_xc [N_NODES * NHEADS * NHID];
__device__ float g_f1 [NHEADS * N_NODES];
__device__ float g_f2 [NHEADS * N_NODES];
__device__ int2  g_wj [N_NODES * NHEADS * KEDGE];  // {w_bits, j*32}, w=0 padded
__device__ float g_h2 [N_NODES * NCLASS];
__device__ float g_f1o[N_NODES];
__device__ float g_f2o[N_NODES];

// ---------------- K1: h = x @ Ws  (32m x 128n tiles, fused f1/f2) ----------------
// grid (4 heads, 128 row-tiles), block 256
__global__ void k_gemm1(const float* __restrict__ X, const float* __restrict__ Ws,
                        const float* __restrict__ a) {
    __shared__ __align__(16) float As[32][36];    // [m][k], pad 36 (16B-aligned rows)
    __shared__ __align__(16) float Bs[32][128];   // [k][n]
    int head = blockIdx.x;
    int m0   = blockIdx.y * 32;
    const float* B = Ws + head * NFEAT * NHID;
    int tid  = threadIdx.x;
    int tx   = tid & 31;          // 32 -> 128 cols (x4)
    int ty   = tid >> 5;          // 8  -> 32 rows  (x4); warp == ty

    int ar  = tid >> 3, ac4 = (tid & 7) * 4;      // A loader: 32 rows x 8 float4
    int bk  = tid >> 5, bn4 = (tid & 31) * 4;     // B loader: 8 k-rows x 32 float4

    float acc[4][4] = {};
    for (int kc = 0; kc < NFEAT; kc += 32) {
        *(float4*)&As[ar][ac4] = *(const float4*)&X[(m0 + ar) * NFEAT + kc + ac4];
        #pragma unroll
        for (int t = 0; t < 4; t++)
            *(float4*)&Bs[bk + t * 8][bn4] = *(const float4*)&B[(kc + bk + t * 8) * NHID + bn4];
        __syncthreads();
        #pragma unroll
        for (int kk = 0; kk < 32; kk++) {
            float av[4];
            #pragma unroll
            for (int i = 0; i < 4; i++) av[i] = As[ty * 4 + i][kk];
            float4 b4 = *(float4*)&Bs[kk][tx * 4];
            float bv[4] = {b4.x, b4.y, b4.z, b4.w};
            #pragma unroll
            for (int i = 0; i < 4; i++)
                #pragma unroll
                for (int j = 0; j < 4; j++)
                    acc[i][j] += av[i] * bv[j];
        }
        __syncthreads();
    }
    // store h + fused f1/f2 (each row fully inside warp ty)
    float a1j[4], a2j[4];
    #pragma unroll
    for (int j = 0; j < 4; j++) {
        a1j[j] = a[head * 256 + tx * 4 + j];
        a2j[j] = a[head * 256 + 128 + tx * 4 + j];
    }
    #pragma unroll
    for (int i = 0; i < 4; i++) {
        int row = m0 + ty * 4 + i;
        *(float4*)&g_h[(size_t)row * 512 + head * 128 + tx * 4] =
            make_float4(acc[i][0], acc[i][1], acc[i][2], acc[i][3]);
        float s1 = 0.f, s2 = 0.f;
        #pragma unroll
        for (int j = 0; j < 4; j++) { s1 += acc[i][j] * a1j[j]; s2 += acc[i][j] * a2j[j]; }
        #pragma unroll
        for (int o = 16; o; o >>= 1) {
            s1 += __shfl_xor_sync(0xffffffffu, s1, o);
            s2 += __shfl_xor_sync(0xffffffffu, s2, o);
        }
        if (tx == 0) {
            g_f1[head * N_NODES + row] = s1;
            g_f2[head * N_NODES + row] = s2;
        }
    }
}

// ---------------- K2: softmax weights, inline dedup, packed {w, j*32} ----------------
__global__ void k_wgt(const int* __restrict__ edge) {
    int tid  = threadIdx.x;
    int row  = blockIdx.x * 4 + (tid >> 7);
    int head = (tid >> 5) & 3;
    int lane = tid & 31;
    int base = row & ~1023;

    int e = edge[row * KEDGE + lane];
    bool valid = (e >= 0);
    unsigned key = valid ? (unsigned)e : (0x40000000u + (unsigned)lane);
    unsigned grp = __match_any_sync(0xffffffffu, key);
    bool uniq = valid && ((__ffs(grp) - 1) == lane);

    float p = 0.f;
    if (uniq) {
        float t = g_f1[head * N_NODES + row] + g_f2[head * N_NODES + base + e];
        float la = (t > 0.f) ? t : ALPHA_LRELU * t;
        p = __expf(la);
    }
    float s = p;
    #pragma unroll
    for (int o = 16; o; o >>= 1) s += __shfl_xor_sync(0xffffffffu, s, o);
    int2 v;
    v.x = __float_as_int(p / s);
    v.y = (valid ? e : 0) * 32;
    g_wj[(row * 4 + head) * KEDGE + lane] = v;
}

// ---------------- K3: layer-1 aggregation, smem tile, int4 wj loads ----------------
// grid (dchunk=4, head=4, part*2+half=8), block 1024, dyn smem 128KB
__global__ void k_attn1_agg() {
    extern __shared__ __align__(16) float tile[];   // [1024 nbrs][32 d]
    int dc   = blockIdx.x;
    int head = blockIdx.y;
    int part = blockIdx.z >> 1;
    int half = blockIdx.z & 1;
    int base = part << 10;
    int tid  = threadIdx.x;

    const float* src = g_h + (size_t)base * 512 + head * 128 + dc * 32;
    #pragma unroll
    for (int i = tid; i < 1024 * 8; i += 1024) {
        int j = i >> 3, d4 = i & 7;
        *(float4*)&tile[j * 32 + d4 * 4] = *(const float4*)&src[(size_t)j * 512 + d4 * 4];
    }
    __syncthreads();

    int lane = tid & 31, warp = tid >> 5;   // 32 warps x 16 rows
    int row0 = base + half * 512 + warp * 16;
    const float* tl = tile + lane;
    #pragma unroll 1
    for (int r = 0; r < 16; r += 2) {
        int rowA = row0 + r, rowB = row0 + r + 1;
        const int4* wjA = (const int4*)(g_wj + (rowA * 4 + head) * KEDGE);
        const int4* wjB = (const int4*)(g_wj + (rowB * 4 + head) * KEDGE);
        float aA = 0.f, aB = 0.f;
        #pragma unroll
        for (int k = 0; k < 16; k++) {
            int4 pA = wjA[k];
            int4 pB = wjB[k];
            aA += __int_as_float(pA.x) * tl[pA.y];
            aA += __int_as_float(pA.z) * tl[pA.w];
            aB += __int_as_float(pB.x) * tl[pB.y];
            aB += __int_as_float(pB.z) * tl[pB.w];
        }
        float oA = aA > 0.f ? aA : expm1f(aA);
        float oB = aB > 0.f ? aB : expm1f(aB);
        g_xc[(size_t)rowA * 512 + head * 128 + dc * 32 + lane] = oA;
        g_xc[(size_t)rowB * 512 + head * 128 + dc * 32 + lane] = oB;
    }
}

// ---------------- K4: h2 = xc @ W_out (warp = 2 rows), fused f1o/f2o ----------------
// grid 256, block 256, dyn smem 64KB (W_out)
__global__ void k_gemm2(const float* __restrict__ W, const float* __restrict__ a_out) {
    extern __shared__ __align__(16) float Wsm[];    // 512*32 floats = 64KB
    int tid = threadIdx.x;
    #pragma unroll
    for (int i = tid; i < 4096; i += 256)
        ((float4*)Wsm)[i] = ((const float4*)W)[i];
    __syncthreads();

    int lane = tid & 31, warp = tid >> 5;
    int row = blockIdx.x * 16 + warp * 2;
    const float4* x0 = (const float4*)(g_xc + (size_t)row * 512);
    const float4* x1 = x0 + 128;

    float acc0 = 0.f, acc1 = 0.f;
    #pragma unroll 16
    for (int q = 0; q < 128; q++) {
        float4 v0 = x0[q];
        float4 v1 = x1[q];
        const float* wp = Wsm + q * 128 + lane;
        float w0 = wp[0], w1 = wp[32], w2 = wp[64], w3 = wp[96];
        acc0 += v0.x * w0 + v0.y * w1 + v0.z * w2 + v0.w * w3;
        acc1 += v1.x * w0 + v1.y * w1 + v1.z * w2 + v1.w * w3;
    }
    g_h2[row * 32 + lane]        = acc0;
    g_h2[(row + 1) * 32 + lane]  = acc1;

    float a1 = a_out[lane], a2 = a_out[32 + lane];
    float s1 = acc0 * a1, s2 = acc0 * a2, s3 = acc1 * a1, s4 = acc1 * a2;
    #pragma unroll
    for (int o = 16; o; o >>= 1) {
        s1 += __shfl_xor_sync(0xffffffffu, s1, o);
        s2 += __shfl_xor_sync(0xffffffffu, s2, o);
        s3 += __shfl_xor_sync(0xffffffffu, s3, o);
        s4 += __shfl_xor_sync(0xffffffffu, s4, o);
    }
    if (lane == 0) {
        g_f1o[row]     = s1;  g_f2o[row]     = s2;
        g_f1o[row + 1] = s3;  g_f2o[row + 1] = s4;
    }
}

// ---------------- K5: layer-2 attention + elu + log_softmax ----------------
__global__ void k_attn2(const int* __restrict__ edge, float* __restrict__ out) {
    int row  = blockIdx.x * 4 + (threadIdx.x >> 5);
    int lane = threadIdx.x & 31;
    int base = row & ~1023;

    int e = edge[row * KEDGE + lane];
    bool valid = (e >= 0);
    unsigned key = valid ? (unsigned)e : (0x40000000u + (unsigned)lane);
    unsigned grp = __match_any_sync(0xffffffffu, key);
    bool uniq = valid && ((__ffs(grp) - 1) == lane);

    float p = 0.f;
    if (uniq) {
        float t = g_f1o[row] + g_f2o[base + e];
        float la = (t > 0.f) ? t : ALPHA_LRELU * t;
        p = __expf(la);
    }
    float s = p;
    #pragma unroll
    for (int o = 16; o; o >>= 1) s += __shfl_xor_sync(0xffffffffu, s, o);
    float wgt = p / s;
    int j = valid ? e : 0;

    float acc = 0.f;
    #pragma unroll 8
    for (int k = 0; k < KEDGE; k++) {
        float wk = __shfl_sync(0xffffffffu, wgt, k);
        int   jk = __shfl_sync(0xffffffffu, j, k);
        acc += wk * g_h2[(base + jk) * 32 + lane];
    }
    float v = acc > 0.f ? acc : expm1f(acc);
    float m2 = v;
    #pragma unroll
    for (int o = 16; o; o >>= 1) m2 = fmaxf(m2, __shfl_xor_sync(0xffffffffu, m2, o));
    float se = __expf(v - m2);
    #pragma unroll
    for (int o = 16; o; o >>= 1) se += __shfl_xor_sync(0xffffffffu, se, o);
    out[row * 32 + lane] = v - m2 - logf(se);
}

// ---------------- launch ----------------
extern "C" void kernel_launch(void* const* d_in, const int* in_sizes, int n_in,
                              void* d_out, int out_size) {
    const float* x     = (const float*)d_in[0];
    const int*   edge  = (const int*)d_in[1];
    const float* Ws    = (const float*)d_in[3];
    const float* a     = (const float*)d_in[4];
    const float* W_out = (const float*)d_in[5];
    const float* a_out = (const float*)d_in[6];
    float* out = (float*)d_out;

    cudaFuncSetAttribute(k_attn1_agg, cudaFuncAttributeMaxDynamicSharedMemorySize,
                         1024 * 32 * sizeof(float));
    cudaFuncSetAttribute(k_gemm2, cudaFuncAttributeMaxDynamicSharedMemorySize,
                         512 * 32 * sizeof(float));

    dim3 g1(4, 128);
    k_gemm1<<<g1, 256>>>(x, Ws, a);
    k_wgt<<<N_NODES / 4, 512>>>(edge);
    dim3 ga(4, 4, 8);
    k_attn1_agg<<<ga, 1024, 1024 * 32 * sizeof(float)>>>();
    k_gemm2<<<256, 256, 512 * 32 * sizeof(float)>>>(W_out, a_out);
    k_attn2<<<N_NODES / 4, 128>>>(edge, out);
}